// round 1
// baseline (speedup 1.0000x reference)
#include <cuda_runtime.h>

// Flow1: K=32, B=4096, ZS=128, ZH=64, HS=50, NF=2
#define KK   32
#define BB   4096
#define ZSv  128
#define ZHv  64
#define HSv  50
#define HSP  52            // HS padded to multiple of 4 (zero-padded)
#define ROWS (KK*BB)       // 131072
#define TPB  128
#define RPC  128           // rows per CTA (thread-per-row)
#define NBLK (ROWS/RPC)    // 1024
#define ZSTR 132           // z row stride in smem (conflict-free LDS.128)

#define SMEM_FLOATS (RPC*ZSTR + HSP*ZHv + 2*ZHv*HSP + HSP + 2*ZHv + RPC*4)
#define SMEM_BYTES  (SMEM_FLOATS * 4)

typedef unsigned long long ull;

__device__ __forceinline__ ull ffma2(ull a, ull b, ull c) {
    ull d;
    asm("fma.rn.f32x2 %0, %1, %2, %3;" : "=l"(d) : "l"(a), "l"(b), "l"(c));
    return d;
}
__device__ __forceinline__ ull pack2(float lo, float hi) {
    ull r;
    asm("mov.b64 %0, {%1, %2};" : "=l"(r) : "f"(lo), "f"(hi));
    return r;
}
__device__ __forceinline__ float2 unpack2(ull v) {
    float lo, hi;
    asm("mov.b64 {%0, %1}, %2;" : "=f"(lo), "=f"(hi) : "l"(v));
    return make_float2(lo, hi);
}

__global__ void __launch_bounds__(TPB) flow_kernel(
    const float* __restrict__ mean, const float* __restrict__ logvar,
    const float* __restrict__ eps,
    const float* __restrict__ W0, const float* __restrict__ b0,
    const float* __restrict__ W1, const float* __restrict__ b1,
    const float* __restrict__ W2, const float* __restrict__ b2,
    float* __restrict__ out)
{
    extern __shared__ float sm[];
    float* zsh     = sm;                    // [RPC][ZSTR] : z1 = cols 0..63, z2 = cols 64..127
    float* w0sh    = zsh  + RPC*ZSTR;       // [HSP][ZHv]  rows j>=50 zero
    float* w1sh    = w0sh + HSP*ZHv;        // [ZHv][HSP]  cols j>=50 zero
    float* w2sh    = w1sh + ZHv*HSP;        // [ZHv][HSP]
    float* b0sh    = w2sh + ZHv*HSP;        // [HSP] (pad zero)
    float* b1sh    = b0sh + HSP;            // [ZHv]
    float* b2sh    = b1sh + ZHv;            // [ZHv]
    float* rowpart = b2sh + ZHv;            // [RPC][4] per-warp partial sums (no atomics)

    const int tid = threadIdx.x;
    const size_t r0    = (size_t)blockIdx.x * RPC;
    const size_t bbase = (size_t)(r0 & (BB-1)) * ZSv;   // rows in a CTA never wrap b

    // ---------------- prologue: z = eps*exp(0.5*lv)+mean, rowsum(lv + eps^2) ----
    #pragma unroll 4
    for (int it = 0; it < RPC; it++) {
        int idx = it * TPB + tid;          // row = it, col = tid
        float ep = eps[r0*ZSv + idx];
        float lv = logvar[bbase + idx];
        float mn = mean[bbase + idx];
        float zv = fmaf(ep, __expf(0.5f*lv), mn);
        zsh[it*ZSTR + tid] = zv;
        float contrib = fmaf(ep, ep, lv);
        #pragma unroll
        for (int o = 16; o; o >>= 1)
            contrib += __shfl_xor_sync(0xFFFFFFFFu, contrib, o);
        if ((tid & 31) == 0) rowpart[it*4 + (tid >> 5)] = contrib;
    }

    float lgsum = 0.f;   // sum of log2(sig) for this thread's row

    // ---------------- 4 flow half-steps: s = 2*i + half -------------------------
    #pragma unroll 1
    for (int s = 0; s < 4; s++) {
        __syncthreads();
        {   // stage weights (zero-padded) into smem
            const float* W0g = W0 + s*(HSv*ZHv);
            #pragma unroll 1
            for (int i = tid; i < HSP*ZHv; i += TPB)
                w0sh[i] = (i < HSv*ZHv) ? W0g[i] : 0.f;
            const float* W1g = W1 + s*(ZHv*HSv);
            const float* W2g = W2 + s*(ZHv*HSv);
            #pragma unroll 1
            for (int i = tid; i < ZHv*HSP; i += TPB) {
                int l = i / HSP;
                int j = i - l*HSP;
                float v1 = 0.f, v2 = 0.f;
                if (j < HSv) { v1 = W1g[l*HSv + j]; v2 = W2g[l*HSv + j]; }
                w1sh[i] = v1;  w2sh[i] = v2;
            }
            if (tid < HSP) b0sh[tid] = (tid < HSv) ? b0[s*HSv + tid] : 0.f;
            if (tid < ZHv) { b1sh[tid] = b1[s*ZHv + tid]; b2sh[tid] = b2[s*ZHv + tid]; }
        }
        __syncthreads();

        const int srcoff = (s & 1) ? 64 : 0;       // half 0: read z1, update z2
        float* zrow = zsh + tid*ZSTR;
        const float* zsrc = zrow + srcoff;

        // ---- h[j] = tanh(W0[j,:]*src + b0[j]), k-pair packed f32x2 ----
        float h[HSP];
        #pragma unroll
        for (int jc = 0; jc < 4; jc++) {
            ull acc[13];
            #pragma unroll
            for (int jj = 0; jj < 13; jj++) acc[jj] = 0ULL;
            #pragma unroll 4
            for (int kq = 0; kq < 16; kq++) {
                ulonglong2 zq = *reinterpret_cast<const ulonglong2*>(zsrc + kq*4);
                #pragma unroll
                for (int jj = 0; jj < 13; jj++) {
                    const int j = jc*13 + jj;
                    ulonglong2 wq = *reinterpret_cast<const ulonglong2*>(w0sh + j*ZHv + kq*4);
                    acc[jj] = ffma2(wq.x, zq.x, acc[jj]);
                    acc[jj] = ffma2(wq.y, zq.y, acc[jj]);
                }
            }
            #pragma unroll
            for (int jj = 0; jj < 13; jj++) {
                const int j = jc*13 + jj;
                float2 p = unpack2(acc[jj]);
                float x = p.x + p.y + b0sh[j];
                // stable tanh: no overflow for any |x|
                float e = __expf(-2.f * fabsf(x));
                float t = __fdividef(1.f - e, 1.f + e);
                h[j] = copysignf(t, x);
            }
        }

        // broadcast-pack h into j-pairs once (reused for all 64 outputs)
        ull hp[26];
        #pragma unroll
        for (int p = 0; p < 26; p++) hp[p] = pack2(h[2*p], h[2*p+1]);

        // ---- mew/sig GEMVs (j-pair packed), update target half + logdet ----
        float* ztgt = zrow + (64 - srcoff);
        #pragma unroll 2
        for (int l = 0; l < ZHv; l++) {
            ull am0 = 0ULL, am1 = 0ULL, as0 = 0ULL, as1 = 0ULL;
            const float* w1r = w1sh + l*HSP;
            const float* w2r = w2sh + l*HSP;
            #pragma unroll
            for (int p = 0; p < 13; p++) {
                ulonglong2 w1q = *reinterpret_cast<const ulonglong2*>(w1r + p*4);
                ulonglong2 w2q = *reinterpret_cast<const ulonglong2*>(w2r + p*4);
                const ull h0 = hp[2*p], h1 = hp[2*p+1];
                am0 = ffma2(w1q.x, h0, am0);
                am1 = ffma2(w1q.y, h1, am1);
                as0 = ffma2(w2q.x, h0, as0);
                as1 = ffma2(w2q.y, h1, as1);
            }
            float2 m0 = unpack2(am0), m1 = unpack2(am1);
            float mew = ((m0.x + m0.y) + (m1.x + m1.y)) + b1sh[l];
            float2 s0 = unpack2(as0), s1 = unpack2(as1);
            float sr  = ((s0.x + s0.y) + (s1.x + s1.y)) + b2sh[l];
            // sr is bounded (|h|<=1, |W2| small): no overflow/underflow paths
            float sig = __fdividef(1.f, 1.f + __expf(-sr));
            ztgt[l] = fmaf(ztgt[l], sig, mew);
            lgsum += __log2f(sig);
        }
    }

    __syncthreads();

    // ---------------- epilogue: z_out then logpz -------------------------------
    #pragma unroll 4
    for (int it = 0; it < RPC; it++) {
        int idx = it * TPB + tid;
        out[r0*ZSv + idx] = zsh[it*ZSTR + tid];
    }
    float rs = rowpart[tid*4+0] + rowpart[tid*4+1] + rowpart[tid*4+2] + rowpart[tid*4+3];
    float logq = -0.5f * ((float)ZSv * 1.8378770664093453f + rs);   // ln(2*pi)
    out[(size_t)ROWS*ZSv + r0 + tid] = logq - lgsum * 0.69314718055994531f; // ln(2)
}

extern "C" void kernel_launch(void* const* d_in, const int* in_sizes, int n_in,
                              void* d_out, int out_size) {
    (void)in_sizes; (void)n_in; (void)out_size;
    const float* mean   = (const float*)d_in[0];
    const float* logvar = (const float*)d_in[1];
    const float* eps    = (const float*)d_in[2];
    const float* W0     = (const float*)d_in[3];
    const float* b0     = (const float*)d_in[4];
    const float* W1     = (const float*)d_in[5];
    const float* b1     = (const float*)d_in[6];
    const float* W2     = (const float*)d_in[7];
    const float* b2     = (const float*)d_in[8];
    float* out = (float*)d_out;

    cudaFuncSetAttribute(flow_kernel, cudaFuncAttributeMaxDynamicSharedMemorySize, SMEM_BYTES);
    flow_kernel<<<NBLK, TPB, SMEM_BYTES>>>(mean, logvar, eps, W0, b0, W1, b1, W2, b2, out);
}